// round 3
// baseline (speedup 1.0000x reference)
#include <cuda_runtime.h>

#define Bsz 128
#define Tsz 2048
#define Fsz 64
#define Usz 128
#define G4  512          // 4*U
#define CH  256          // time-chunk length
#define NCH (Tsz / CH)   // 8 chunks

// Chunked scratch (allocation-free contract: __device__ globals). ~145 MB total.
__device__ float g_xw1c[(size_t)CH * Bsz * G4];   // 64 MB: x@W1+b1 for chunk, [tc][b][512]
__device__ float g_h1c [(size_t)CH * Bsz * Usz];  // 16 MB: layer-1 h for chunk, [tc][b][128]
__device__ float g_xw2c[(size_t)CH * Bsz * G4];   // 64 MB: h1@W2+b2 for chunk
// Carried recurrent state (h,c per layer), [b][u]
__device__ float g_h1s[Bsz * Usz];
__device__ float g_c1s[Bsz * Usz];
__device__ float g_h2s[Bsz * Usz];
__device__ float g_c2s[Bsz * Usz];

__device__ __forceinline__ float sigmoidf(float x) {
    return __fdividef(1.0f, 1.0f + __expf(-x));
}

// ---------------------------------------------------------------------------
// k_xw1: g_xw1c[tc,b,g] = b1[g] + sum_f x[b,t0+tc,f] * W1[f,g]
// One W1 column per thread in registers; 4 (t,b)-rows per iteration.
// ---------------------------------------------------------------------------
__global__ __launch_bounds__(512, 1) void k_xw1(const float* __restrict__ x,
                                                const float* __restrict__ W1,
                                                const float* __restrict__ b1,
                                                int t0) {
    const int g = threadIdx.x;
    float wc[Fsz];
#pragma unroll
    for (int f = 0; f < Fsz; f++) wc[f] = W1[f * G4 + g];
    const float bias = b1[g];

    __shared__ float xs[4][Fsz];
    const int total = CH * Bsz;
    for (int base = blockIdx.x * 4; base < total; base += gridDim.x * 4) {
        if (threadIdx.x < 4 * Fsz) {
            int rr = threadIdx.x / Fsz, f = threadIdx.x % Fsz;
            int row = base + rr;                  // row = tc*B + b
            int t = t0 + row / Bsz, b = row % Bsz;
            xs[rr][f] = x[((size_t)b * Tsz + t) * Fsz + f];
        }
        __syncthreads();
        float a0 = bias, a1 = bias, a2 = bias, a3 = bias;
#pragma unroll
        for (int f = 0; f < Fsz; f += 4) {
            float4 x0 = *(const float4*)&xs[0][f];
            float4 x1 = *(const float4*)&xs[1][f];
            float4 x2 = *(const float4*)&xs[2][f];
            float4 x3 = *(const float4*)&xs[3][f];
            float w0 = wc[f], w1 = wc[f + 1], w2 = wc[f + 2], w3 = wc[f + 3];
            a0 += x0.x * w0 + x0.y * w1 + x0.z * w2 + x0.w * w3;
            a1 += x1.x * w0 + x1.y * w1 + x1.z * w2 + x1.w * w3;
            a2 += x2.x * w0 + x2.y * w1 + x2.z * w2 + x2.w * w3;
            a3 += x3.x * w0 + x3.y * w1 + x3.z * w2 + x3.w * w3;
        }
        g_xw1c[(size_t)(base + 0) * G4 + g] = a0;
        g_xw1c[(size_t)(base + 1) * G4 + g] = a1;
        g_xw1c[(size_t)(base + 2) * G4 + g] = a2;
        g_xw1c[(size_t)(base + 3) * G4 + g] = a3;
        __syncthreads();
    }
}

// ---------------------------------------------------------------------------
// k_xw2: g_xw2c[tc,b,g] = b2[g] + sum_u g_h1c[tc,b,u] * W2[u,g]
// K=128: 64 rows of the W2 column in registers, 64 rows in smem.
// ---------------------------------------------------------------------------
#define XW2_RREG 64
#define XW2_RSM  (Usz - XW2_RREG)   // 64

__global__ __launch_bounds__(512, 1) void k_xw2(const float* __restrict__ W2,
                                                const float* __restrict__ b2) {
    extern __shared__ float sm[];
    float* w2s = sm;                      // [XW2_RSM][512]
    float* xs  = sm + XW2_RSM * G4;       // [2][128]
    const int g = threadIdx.x;

    float wc[XW2_RREG];
#pragma unroll
    for (int j = 0; j < XW2_RREG; j++) wc[j] = W2[j * G4 + g];
    for (int idx = threadIdx.x; idx < XW2_RSM * G4; idx += blockDim.x)
        w2s[idx] = W2[XW2_RREG * G4 + idx];   // rows 64..127, contiguous
    const float bias = b2[g];
    __syncthreads();

    const int total = CH * Bsz;
    for (int base = blockIdx.x * 2; base < total; base += gridDim.x * 2) {
        if (threadIdx.x < 2 * Usz) {
            int rr = threadIdx.x / Usz, u = threadIdx.x % Usz;
            xs[rr * Usz + u] = g_h1c[(size_t)(base + rr) * Usz + u];
        }
        __syncthreads();
        float a0 = bias, a1 = bias;
#pragma unroll
        for (int j = 0; j < XW2_RREG; j += 4) {
            float4 x0 = *(const float4*)&xs[j];
            float4 x1 = *(const float4*)&xs[Usz + j];
            a0 += x0.x * wc[j] + x0.y * wc[j + 1] + x0.z * wc[j + 2] + x0.w * wc[j + 3];
            a1 += x1.x * wc[j] + x1.y * wc[j + 1] + x1.z * wc[j + 2] + x1.w * wc[j + 3];
        }
#pragma unroll
        for (int jj = 0; jj < XW2_RSM; jj += 4) {
            float4 x0 = *(const float4*)&xs[XW2_RREG + jj];
            float4 x1 = *(const float4*)&xs[Usz + XW2_RREG + jj];
            float w0 = w2s[(jj + 0) * G4 + g];
            float w1 = w2s[(jj + 1) * G4 + g];
            float w2 = w2s[(jj + 2) * G4 + g];
            float w3 = w2s[(jj + 3) * G4 + g];
            a0 += x0.x * w0 + x0.y * w1 + x0.z * w2 + x0.w * w3;
            a1 += x1.x * w0 + x1.y * w1 + x1.z * w2 + x1.w * w3;
        }
        g_xw2c[(size_t)(base + 0) * G4 + g] = a0;
        g_xw2c[(size_t)(base + 1) * G4 + g] = a1;
        __syncthreads();
    }
}

// ---------------------------------------------------------------------------
// Recurrent kernel over one time chunk: one CTA per batch element, 256 thr.
// Thread t owns z columns {2t, 2t+1}. Weights: rows 0..63 as float2 in
// registers, rows 64..127 in smem. h broadcast via smem; c in registers of
// threads 0..127. State carried in g_{h,c}{1,2}s between chunk launches.
// ---------------------------------------------------------------------------
#define RREG 64
#define RSM  (Usz - RREG)   // 64

template <bool LAYER1>
__global__ __launch_bounds__(256, 1) void lstm_rec(const float* __restrict__ Uw,
                                                   const float* __restrict__ Wd,
                                                   const float* __restrict__ bd,
                                                   float* __restrict__ out,
                                                   int first, int last) {
    extern __shared__ float sm[];
    float2* ws  = (float2*)sm;                 // [RSM][256] float2
    float* hbuf = sm + (size_t)RSM * 256 * 2;  // 128 floats
    float* zbuf = hbuf + Usz;                  // 512 floats

    const int tid = threadIdx.x;
    const int b   = blockIdx.x;
    const float* __restrict__ xw = LAYER1 ? (const float*)g_xw1c : (const float*)g_xw2c;
    float* __restrict__ hs = LAYER1 ? g_h1s : g_h2s;
    float* __restrict__ cs = LAYER1 ? g_c1s : g_c2s;

    // Load weights
    float2 wr[RREG];
#pragma unroll
    for (int r = 0; r < RREG; r++)
        wr[r] = *(const float2*)&Uw[r * G4 + 2 * tid];
#pragma unroll
    for (int r = 0; r < RSM; r++)
        ws[r * 256 + tid] = *(const float2*)&Uw[(RREG + r) * G4 + 2 * tid];

    float c = 0.0f;
    if (tid < Usz) {
        hbuf[tid] = first ? 0.0f : hs[b * Usz + tid];
        if (!first) c = cs[b * Usz + tid];
    }
    __syncthreads();

    float2 cur = *(const float2*)&xw[(size_t)b * G4 + 2 * tid];  // tc = 0

    for (int tc = 0; tc < CH; tc++) {
        float2 nxt = make_float2(0.0f, 0.0f);
        if (tc + 1 < CH)
            nxt = *(const float2*)&xw[((size_t)(tc + 1) * Bsz + b) * G4 + 2 * tid];

        float ax = cur.x, ay = cur.y;
#pragma unroll
        for (int r = 0; r < RREG; r += 4) {
            float4 h4 = *(const float4*)&hbuf[r];
            ax += h4.x * wr[r    ].x;  ay += h4.x * wr[r    ].y;
            ax += h4.y * wr[r + 1].x;  ay += h4.y * wr[r + 1].y;
            ax += h4.z * wr[r + 2].x;  ay += h4.z * wr[r + 2].y;
            ax += h4.w * wr[r + 3].x;  ay += h4.w * wr[r + 3].y;
        }
#pragma unroll
        for (int r = 0; r < RSM; r += 4) {
            float4 h4 = *(const float4*)&hbuf[RREG + r];
            float2 w0 = ws[(r + 0) * 256 + tid];
            float2 w1 = ws[(r + 1) * 256 + tid];
            float2 w2 = ws[(r + 2) * 256 + tid];
            float2 w3 = ws[(r + 3) * 256 + tid];
            ax += h4.x * w0.x;  ay += h4.x * w0.y;
            ax += h4.y * w1.x;  ay += h4.y * w1.y;
            ax += h4.z * w2.x;  ay += h4.z * w2.y;
            ax += h4.w * w3.x;  ay += h4.w * w3.y;
        }
        *(float2*)&zbuf[2 * tid] = make_float2(ax, ay);
        __syncthreads();

        if (tid < Usz) {
            float ig = sigmoidf(zbuf[tid]);
            float fg = sigmoidf(zbuf[Usz + tid]);
            float gg = fmaxf(zbuf[2 * Usz + tid], 0.0f);
            float og = sigmoidf(zbuf[3 * Usz + tid]);
            c = fg * c + ig * gg;
            float h = og * fmaxf(c, 0.0f);
            hbuf[tid] = h;
            if (LAYER1)
                g_h1c[((size_t)tc * Bsz + b) * Usz + tid] = h;
        }
        __syncthreads();
        cur = nxt;
    }

    // Persist state for next chunk
    if (tid < Usz) {
        hs[b * Usz + tid] = hbuf[tid];
        cs[b * Usz + tid] = c;
    }

    if (!LAYER1 && last) {
        // Final dense: out[b] = sum_u h[u]*Wd[u] + bd
        float p = (tid < Usz) ? hbuf[tid] * Wd[tid] : 0.0f;
        zbuf[tid] = p;
        __syncthreads();
        if (tid == 0) {
            float s = bd[0];
#pragma unroll 8
            for (int u = 0; u < Usz; u++) s += zbuf[u];
            out[b] = s;
        }
    }
}

// ---------------------------------------------------------------------------
extern "C" void kernel_launch(void* const* d_in, const int* in_sizes, int n_in,
                              void* d_out, int out_size) {
    const float* x  = (const float*)d_in[0];
    const float* W1 = (const float*)d_in[1];
    const float* U1 = (const float*)d_in[2];
    const float* b1 = (const float*)d_in[3];
    const float* W2 = (const float*)d_in[4];
    const float* U2 = (const float*)d_in[5];
    const float* b2 = (const float*)d_in[6];
    const float* Wd = (const float*)d_in[7];
    const float* bd = (const float*)d_in[8];
    float* out = (float*)d_out;

    const size_t sm_xw2 = (size_t)(XW2_RSM * G4 + 2 * Usz) * sizeof(float);       // ~132 KB
    const size_t sm_rec = ((size_t)RSM * 256 * 2 + Usz + G4) * sizeof(float);     // ~134 KB

    (void)cudaFuncSetAttribute((const void*)k_xw2,
                         cudaFuncAttributeMaxDynamicSharedMemorySize, (int)sm_xw2);
    (void)cudaFuncSetAttribute((const void*)lstm_rec<true>,
                         cudaFuncAttributeMaxDynamicSharedMemorySize, (int)sm_rec);
    (void)cudaFuncSetAttribute((const void*)lstm_rec<false>,
                         cudaFuncAttributeMaxDynamicSharedMemorySize, (int)sm_rec);

    for (int k = 0; k < NCH; k++) {
        const int first = (k == 0);
        const int last  = (k == NCH - 1);
        // layer-1 input projection for this chunk
        k_xw1<<<148, 512>>>(x, W1, b1, k * CH);
        // layer-1 recurrence for this chunk (stores h1 chunk + state)
        lstm_rec<true><<<Bsz, 256, sm_rec>>>(U1, Wd, bd, out, first, last);
        // layer-2 input projection for this chunk
        k_xw2<<<148, 512, sm_xw2>>>(W2, b2);
        // layer-2 recurrence for this chunk (+ final dense on last chunk)
        lstm_rec<false><<<Bsz, 256, sm_rec>>>(U2, Wd, bd, out, first, last);
    }
}